// round 16
// baseline (speedup 1.0000x reference)
#include <cuda_runtime.h>
#include <cstdint>
#include <math.h>

#define Bn 16
#define Ln 2048
#define Mn 32000
#define Dn 512
#define NCHUNK 16           // chunks per batch in k24 (128 tokens each)
#define NBLK   500          // k_ip blocks (4 groups of 16 tokens each)
#define ESTRIDE 512         // padded esum stride per batch (pad stays 0)
#define GRPS   4            // token-groups per k_ip block
#define GTOK   16           // tokens per group
#define PSTRIDE 36          // padded floats per partial row
#define NORMROW 256         // norm partial rows start index (16 rows)
#define IP_SMEM (GTOK * Dn * 4 + (NORMROW + GTOK) * PSTRIDE * 4)  // 71936 B

// ---------------- scratch ----------------
__device__ float g_inv_p[Ln];
__device__ float g_inv_q;                // inv norm of emb[Mn]
__device__ float g_partial[Bn * NCHUNK * Dn];
__device__ float g_wpart[Bn * NCHUNK];
__device__ float g_sel[Bn * Dn];
__device__ float g_esum[Bn * ESTRIDE];   // pad entries never written (stay 0)
__device__ float g_tgtip[Bn];

__device__ __forceinline__ float dot4(float4 a, float4 b) {
    return a.x * b.x + a.y * b.y + a.z * b.z + a.w * b.w;
}

// packed 2xfp32 fma: d = a*b + d
#define FMA2(d, a, b) \
    asm("fma.rn.f32x2 %0, %1, %2, %3;" : "=l"(d) : "l"(a), "l"(b), "l"(d))

__device__ __forceinline__ float unpack_add(unsigned long long v) {
    float lo, hi;
    asm("mov.b64 {%0,%1}, %2;" : "=f"(lo), "=f"(hi) : "l"(v));
    return lo + hi;
}

#define CP_ASYNC16(dst32, src) \
    asm volatile("cp.async.cg.shared.global [%0], [%1], 16;" \
                 :: "r"(dst32), "l"(src))
#define CP_COMMIT() asm volatile("cp.async.commit_group;" ::: "memory")
#define CP_WAIT0()  asm volatile("cp.async.wait_group 0;" ::: "memory")

// ---------------- K0: pos-row inverse norms + q-row inv norm -------------
__global__ void k_pnorm(const float* __restrict__ emb,
                        const float* __restrict__ pos) {
    int warp = (blockIdx.x * blockDim.x + threadIdx.x) >> 5;
    int lane = threadIdx.x & 31;
    if (warp > Ln) return;
    const float* r = (warp < Ln) ? pos + (size_t)warp * Dn
                                 : emb + (size_t)Mn * Dn;
    const float4* r4 = (const float4*)r;
    float s = 0.f;
#pragma unroll
    for (int j = 0; j < 4; j++) { float4 v = r4[lane + 32 * j]; s += dot4(v, v); }
#pragma unroll
    for (int o = 16; o; o >>= 1) s += __shfl_xor_sync(0xffffffffu, s, o);
    if (lane == 0) {
        float inv = 1.0f / fmaxf(sqrtf(s), 1.0f);
        if (warp < Ln) g_inv_p[warp] = inv; else g_inv_q = inv;
    }
}

// ---------------- K1: fused logits + emb norms + exp + weighted sum ------
// grid (NCHUNK, Bn), block 512. Chunk = 128 tokens. Single emb-row touch.
__global__ __launch_bounds__(512) void k24(
    const float* __restrict__ emb, const float* __restrict__ pos,
    const int* __restrict__ x, const int* __restrict__ mask_idx) {
    __shared__ __align__(16) float qs[Dn];
    __shared__ __align__(16) float ps[Dn];
    __shared__ __align__(16) float4 wacc[16 * 128];   // 32KB warp accumulators
    __shared__ float wes[16];
    int b = blockIdx.y, c = blockIdx.x;
    int tid = threadIdx.x;
    int wid = tid >> 5, lane = tid & 31;
    int mb = mask_idx[b];

    qs[tid] = emb[(size_t)Mn * Dn + tid] * g_inv_q;
    ps[tid] = pos[(size_t)mb * Dn + tid] * g_inv_p[mb];
    __syncthreads();

    const float4* q4 = (const float4*)qs;
    const float4* p4 = (const float4*)ps;
    float4 acc[4];
#pragma unroll
    for (int j = 0; j < 4; j++) acc[j] = make_float4(0.f, 0.f, 0.f, 0.f);
    float es = 0.f;

#pragma unroll 1
    for (int k = 0; k < 8; k++) {
        int i = wid * 8 + k;            // 0..127 in chunk
        int m = c * 128 + i;
        int tok = (m == mb) ? Mn : x[b * Ln + m];
        const float4* er = (const float4*)(emb + (size_t)tok * Dn);
        const float4* pr = (const float4*)(pos + (size_t)m * Dn);
        float4 e[4];
        float dc = 0.f, en = 0.f, dp = 0.f;
#pragma unroll
        for (int j = 0; j < 4; j++) {
            e[j] = er[lane + 32 * j];
            float4 p = pr[lane + 32 * j];
            dc += dot4(e[j], q4[lane + 32 * j]);
            en += dot4(e[j], e[j]);
            dp += dot4(p, p4[lane + 32 * j]);
        }
        float send1 = (lane & 1) ? dc : en;
        float recv1 = __shfl_xor_sync(0xffffffffu, send1, 1);
        float v = ((lane & 1) ? en : dc) + recv1;
        float u = dp;
#pragma unroll
        for (int o = 2; o <= 16; o <<= 1) {
            v += __shfl_xor_sync(0xffffffffu, v, o);
            u += __shfl_xor_sync(0xffffffffu, u, o);
        }
        u += __shfl_xor_sync(0xffffffffu, u, 1);         // full dp sum
        float enq = __shfl_xor_sync(0xffffffffu, v, 1);  // even lanes: en sum
        float wgt = 0.f;
        if (lane == 0) {
            float inve = 1.0f / fmaxf(sqrtf(enq), 1.0f);
            float s = v * inve + u * g_inv_p[m];
            float ex = __expf(s * (1.0f / 32.0f));
            es += ex;
            wgt = ex * inve;
        }
        wgt = __shfl_sync(0xffffffffu, wgt, 0);
#pragma unroll
        for (int j = 0; j < 4; j++) {
            acc[j].x += wgt * e[j].x;
            acc[j].y += wgt * e[j].y;
            acc[j].z += wgt * e[j].z;
            acc[j].w += wgt * e[j].w;
        }
    }
#pragma unroll
    for (int j = 0; j < 4; j++) wacc[wid * 128 + lane + 32 * j] = acc[j];
    if (lane == 0) wes[wid] = es;
    __syncthreads();
    if (tid == 0) {
        float sw = 0.f;
#pragma unroll
        for (int i = 0; i < 16; i++) sw += wes[i];
        g_wpart[b * NCHUNK + c] = sw;
    }
    if (tid < 128) {
        float4 s = make_float4(0.f, 0.f, 0.f, 0.f);
#pragma unroll
        for (int w = 0; w < 16; w++) {
            float4 a = wacc[w * 128 + tid];
            s.x += a.x; s.y += a.y; s.z += a.z; s.w += a.w;
        }
        ((float4*)g_partial)[(size_t)(b * NCHUNK + c) * 128 + tid] = s;
    }
}

// ---------------- K2: reduce partials, normalize -> sel ----------------
__global__ __launch_bounds__(512) void k_sel(float* __restrict__ out_sel) {
    int b = blockIdx.x, tid = threadIdx.x;
    __shared__ float sinv;
    if (tid < 32) {
        float v = (tid < NCHUNK) ? g_wpart[b * NCHUNK + tid] : 0.f;
#pragma unroll
        for (int o = 16; o; o >>= 1) v += __shfl_xor_sync(0xffffffffu, v, o);
        if (tid == 0) sinv = 1.0f / v;
    }
    __syncthreads();
    float s = 0.f;
#pragma unroll
    for (int c = 0; c < NCHUNK; c++) s += g_partial[(b * NCHUNK + c) * Dn + tid];
    s *= sinv;
    g_sel[b * Dn + tid] = s;
    if (out_sel) out_sel[b * Dn + tid] = s;
}

// ---------------- K3: vocab inner products, cp.async-staged rows ---------
// grid NBLK=500, block 128 (4 warps), 3 blocks/SM (72KB dynamic smem).
// Per group: 128 threads cp.async the 16 emb rows (32KB) into smem; all
// warps compute within-lane partial dots from smem (LDS, no global stalls).
// Next group's copies are issued during phase 2 (copy/compute overlap).
__global__ __launch_bounds__(128, 3) void k_ip(
    const float* __restrict__ emb, const int* __restrict__ x,
    const int* __restrict__ mask_idx) {
    extern __shared__ __align__(16) float smem[];
    float* rbuf = smem;                         // GTOK*Dn floats (32KB)
    float* part = smem + GTOK * Dn;             // (NORMROW+GTOK)*PSTRIDE
    int tid = threadIdx.x;
    int w = tid >> 5, lane = tid & 31;
    int b0 = w * 4;

    // issue group-0 copies first (overlap with selp loads)
    unsigned int rbase = (unsigned int)__cvta_generic_to_shared(rbuf);
    {
        const float* src = emb + (size_t)(blockIdx.x * GRPS) * GTOK * Dn;
#pragma unroll
        for (int j = 0; j < 16; j++) {
            int idx = j * 128 + tid;
            CP_ASYNC16(rbase + idx * 16, (const float4*)src + idx);
        }
        CP_COMMIT();
    }

    // sel cache for this warp's 4 batches
    unsigned long long selp[4][8];
#pragma unroll
    for (int bb = 0; bb < 4; bb++) {
        const ulonglong2* s2 = (const ulonglong2*)(g_sel + (size_t)(b0 + bb) * Dn);
#pragma unroll
        for (int j = 0; j < 4; j++) {
            ulonglong2 q = s2[lane + 32 * j];
            selp[bb][2 * j] = q.x;
            selp[bb][2 * j + 1] = q.y;
        }
    }

    // phase-2 ownership: round k: row r = w*64 + k*32 + lane, b=r>>4, t=r&15
    int pb[2], ptgt[2];
    float es[2] = {0.f, 0.f};
#pragma unroll
    for (int k = 0; k < 2; k++) {
        int r = w * 64 + k * 32 + lane;
        pb[k] = r >> 4;
        ptgt[k] = x[pb[k] * Ln + mask_idx[pb[k]]];
    }
    int myt = lane & 15;   // token index within group for phase 2

#pragma unroll 1
    for (int g = 0; g < GRPS; g++) {
        int t0 = (blockIdx.x * GRPS + g) * GTOK;
        CP_WAIT0();
        __syncthreads();
        // ---- phase 1: compute from smem rows ----
        const ulonglong2* r2 = (const ulonglong2*)rbuf;
#pragma unroll 2
        for (int t = 0; t < GTOK; t++) {
            unsigned long long ep[8];
#pragma unroll
            for (int j = 0; j < 4; j++) {
                ulonglong2 q = r2[t * 128 + lane + 32 * j];
                ep[2 * j] = q.x;
                ep[2 * j + 1] = q.y;
            }
            unsigned long long acc2[4] = {0ull, 0ull, 0ull, 0ull};
#pragma unroll
            for (int j = 0; j < 8; j++) {
                FMA2(acc2[0], ep[j], selp[0][j]);
                FMA2(acc2[1], ep[j], selp[1][j]);
                FMA2(acc2[2], ep[j], selp[2][j]);
                FMA2(acc2[3], ep[j], selp[3][j]);
            }
#pragma unroll
            for (int bb = 0; bb < 4; bb++)
                part[((b0 + bb) * GTOK + t) * PSTRIDE + lane] =
                    unpack_add(acc2[bb]);
            if (w == (t & 3)) {   // norm partial: one warp per token
                unsigned long long nacc = 0ull;
#pragma unroll
                for (int j = 0; j < 8; j++) FMA2(nacc, ep[j], ep[j]);
                part[(NORMROW + t) * PSTRIDE + lane] = unpack_add(nacc);
            }
        }
        __syncthreads();   // part complete; rbuf no longer read
        // issue next group's copies (overlaps phase 2)
        if (g + 1 < GRPS) {
            const float* src = emb + (size_t)(t0 + GTOK) * Dn;
#pragma unroll
            for (int j = 0; j < 16; j++) {
                int idx = j * 128 + tid;
                CP_ASYNC16(rbase + idx * 16, (const float4*)src + idx);
            }
            CP_COMMIT();
        }
        // ---- phase 2 ----
        float ninv;
        {
            const float4* nr = (const float4*)&part[(NORMROW + myt) * PSTRIDE];
            float4 n0 = nr[0], n1 = nr[1], n2 = nr[2], n3 = nr[3];
            float4 n4 = nr[4], n5 = nr[5], n6 = nr[6], n7 = nr[7];
            float nx = ((n0.x + n1.x) + (n2.x + n3.x)) + ((n4.x + n5.x) + (n6.x + n7.x));
            float ny = ((n0.y + n1.y) + (n2.y + n3.y)) + ((n4.y + n5.y) + (n6.y + n7.y));
            float nz = ((n0.z + n1.z) + (n2.z + n3.z)) + ((n4.z + n5.z) + (n6.z + n7.z));
            float nw = ((n0.w + n1.w) + (n2.w + n3.w)) + ((n4.w + n5.w) + (n6.w + n7.w));
            float nsum = (nx + ny) + (nz + nw);
            ninv = 1.0f / fmaxf(sqrtf(nsum), 1.0f);
        }
#pragma unroll
        for (int k = 0; k < 2; k++) {
            int r = w * 64 + k * 32 + lane;
            const float4* row = (const float4*)&part[r * PSTRIDE];
            float4 s0 = row[0], s1 = row[1], s2 = row[2], s3 = row[3];
            float4 s4 = row[4], s5 = row[5], s6 = row[6], s7 = row[7];
            float4 u;
            u.x = ((s0.x + s1.x) + (s2.x + s3.x)) + ((s4.x + s5.x) + (s6.x + s7.x));
            u.y = ((s0.y + s1.y) + (s2.y + s3.y)) + ((s4.y + s5.y) + (s6.y + s7.y));
            u.z = ((s0.z + s1.z) + (s2.z + s3.z)) + ((s4.z + s5.z) + (s6.z + s7.z));
            u.w = ((s0.w + s1.w) + (s2.w + s3.w)) + ((s4.w + s5.w) + (s6.w + s7.w));
            float dot = (u.x + u.y) + (u.z + u.w);
            int tok = t0 + myt;
            float v = dot * ninv;
            if (tok == ptgt[k]) g_tgtip[pb[k]] = v;
            es[k] += __expf(v);
        }
        __syncthreads();   // part free before next phase 1 writes
    }
    // block-level exp-sum: 16 lanes share each (round, half) batch
#pragma unroll
    for (int k = 0; k < 2; k++) {
        float e = es[k];
#pragma unroll
        for (int o = 8; o; o >>= 1) e += __shfl_xor_sync(0xffffffffu, e, o);
        if ((lane & 15) == 0) g_esum[pb[k] * ESTRIDE + blockIdx.x] = e;
    }
}

// ---------------- K4: final loss ----------------
__global__ __launch_bounds__(512) void k_final(float* __restrict__ out_loss) {
    __shared__ float lp[16];
    int w = threadIdx.x >> 5, lane = threadIdx.x & 31;   // 16 warps, warp per b
    const float4* p = (const float4*)&g_esum[w * ESTRIDE];
    float s = 0.f;
#pragma unroll
    for (int q = 0; q < 4; q++) {
        float4 v = p[lane + 32 * q];
        s += (v.x + v.y) + (v.z + v.w);
    }
#pragma unroll
    for (int o = 16; o; o >>= 1) s += __shfl_xor_sync(0xffffffffu, s, o);
    if (lane == 0) lp[w] = g_tgtip[w] - logf(s);
    __syncthreads();
    if (threadIdx.x == 0) {
        float t = 0.f;
#pragma unroll
        for (int b = 0; b < Bn; b++) t += lp[b];
        if (out_loss) *out_loss = -t * (1.0f / Bn);
    }
}

// ---------------- host ----------------
extern "C" void kernel_launch(void* const* d_in, const int* in_sizes, int n_in,
                              void* d_out, int out_size) {
    const int* x = nullptr;
    const int* mask_idx = nullptr;
    const float* emb = nullptr;
    const float* pos = nullptr;
    for (int i = 0; i < n_in; i++) {
        switch (in_sizes[i]) {
            case Bn * Ln:        x = (const int*)d_in[i]; break;
            case Bn:             mask_idx = (const int*)d_in[i]; break;
            case (Mn + 1) * Dn:  emb = (const float*)d_in[i]; break;
            case Ln * Dn:        pos = (const float*)d_in[i]; break;
            default: break;
        }
    }

    float* out = (float*)d_out;
    float* lossp;
    float* selp;
    if (out_size == 1 + Bn * Dn) { lossp = out; selp = out + 1; }
    else if (out_size == Bn * Dn) { lossp = nullptr; selp = out; }
    else if (out_size == 1) { lossp = out; selp = nullptr; }
    else { lossp = out; selp = (out_size > 1) ? out + 1 : nullptr; }

    cudaFuncSetAttribute(k_ip, cudaFuncAttributeMaxDynamicSharedMemorySize,
                         IP_SMEM);

    // K0: pos + q-row inverse norms
    {
        int totalWarps = Ln + 1;
        int blocks = (totalWarps * 32 + 255) / 256;
        k_pnorm<<<blocks, 256>>>(emb, pos);
    }
    // K1: fused logits + emb norms + exp + weighted-sum (single row touch)
    {
        dim3 g(NCHUNK, Bn);
        k24<<<g, 512>>>(emb, pos, x, mask_idx);
    }
    // K2: reduce -> sel_output
    k_sel<<<Bn, 512>>>(selp);
    // K3: vocab inner products (cp.async staged) + norms + exp-sums
    k_ip<<<NBLK, 128, IP_SMEM>>>(emb, x, mask_idx);
    // K4: final loss
    k_final<<<1, 512>>>(lossp);
}

// round 17
// speedup vs baseline: 1.0946x; 1.0946x over previous
#include <cuda_runtime.h>
#include <cstdint>
#include <math.h>

#define Bn 16
#define Ln 2048
#define Mn 32000
#define Dn 512
#define NCHUNK 16           // chunks per batch in k24 (128 tokens each)
#define NBLK   444          // k_ip blocks = 3/SM x 148 SMs (single wave)
#define NGRP   2000         // 16-token groups over the vocab
#define ESTRIDE 512         // padded esum stride per batch (pad stays 0)
#define GTOK   16           // tokens per group
#define PSTRIDE 36          // padded floats per partial row
#define NORMROW 256         // norm partial rows start index (16 rows)
#define IP_SMEM (GTOK * Dn * 4 + (NORMROW + GTOK) * PSTRIDE * 4)  // 71936 B

// ---------------- scratch ----------------
__device__ float g_inv_p[Ln];
__device__ float g_inv_q;                // inv norm of emb[Mn]
__device__ float g_partial[Bn * NCHUNK * Dn];
__device__ float g_wpart[Bn * NCHUNK];
__device__ float g_sel[Bn * Dn];
__device__ float g_esum[Bn * ESTRIDE];   // pad entries never written (stay 0)
__device__ float g_tgtip[Bn];

__device__ __forceinline__ float dot4(float4 a, float4 b) {
    return a.x * b.x + a.y * b.y + a.z * b.z + a.w * b.w;
}

// packed 2xfp32 fma: d = a*b + d
#define FMA2(d, a, b) \
    asm("fma.rn.f32x2 %0, %1, %2, %3;" : "=l"(d) : "l"(a), "l"(b), "l"(d))

__device__ __forceinline__ float unpack_add(unsigned long long v) {
    float lo, hi;
    asm("mov.b64 {%0,%1}, %2;" : "=f"(lo), "=f"(hi) : "l"(v));
    return lo + hi;
}

#define CP_ASYNC16(dst32, src) \
    asm volatile("cp.async.cg.shared.global [%0], [%1], 16;" \
                 :: "r"(dst32), "l"(src))
#define CP_COMMIT() asm volatile("cp.async.commit_group;" ::: "memory")
#define CP_WAIT0()  asm volatile("cp.async.wait_group 0;" ::: "memory")

// ---------------- K0: pos-row inverse norms + q-row inv norm -------------
__global__ void k_pnorm(const float* __restrict__ emb,
                        const float* __restrict__ pos) {
    int warp = (blockIdx.x * blockDim.x + threadIdx.x) >> 5;
    int lane = threadIdx.x & 31;
    if (warp > Ln) return;
    const float* r = (warp < Ln) ? pos + (size_t)warp * Dn
                                 : emb + (size_t)Mn * Dn;
    const float4* r4 = (const float4*)r;
    float s = 0.f;
#pragma unroll
    for (int j = 0; j < 4; j++) { float4 v = r4[lane + 32 * j]; s += dot4(v, v); }
#pragma unroll
    for (int o = 16; o; o >>= 1) s += __shfl_xor_sync(0xffffffffu, s, o);
    if (lane == 0) {
        float inv = 1.0f / fmaxf(sqrtf(s), 1.0f);
        if (warp < Ln) g_inv_p[warp] = inv; else g_inv_q = inv;
    }
}

// ---------------- K1: fused logits + emb norms + exp + weighted sum ------
// grid (NCHUNK, Bn), block 512. Chunk = 128 tokens. Single emb-row touch.
__global__ __launch_bounds__(512) void k24(
    const float* __restrict__ emb, const float* __restrict__ pos,
    const int* __restrict__ x, const int* __restrict__ mask_idx) {
    __shared__ __align__(16) float qs[Dn];
    __shared__ __align__(16) float ps[Dn];
    __shared__ __align__(16) float4 wacc[16 * 128];   // 32KB warp accumulators
    __shared__ float wes[16];
    int b = blockIdx.y, c = blockIdx.x;
    int tid = threadIdx.x;
    int wid = tid >> 5, lane = tid & 31;
    int mb = mask_idx[b];

    qs[tid] = emb[(size_t)Mn * Dn + tid] * g_inv_q;
    ps[tid] = pos[(size_t)mb * Dn + tid] * g_inv_p[mb];
    __syncthreads();

    const float4* q4 = (const float4*)qs;
    const float4* p4 = (const float4*)ps;
    float4 acc[4];
#pragma unroll
    for (int j = 0; j < 4; j++) acc[j] = make_float4(0.f, 0.f, 0.f, 0.f);
    float es = 0.f;

#pragma unroll 1
    for (int k = 0; k < 8; k++) {
        int i = wid * 8 + k;            // 0..127 in chunk
        int m = c * 128 + i;
        int tok = (m == mb) ? Mn : x[b * Ln + m];
        const float4* er = (const float4*)(emb + (size_t)tok * Dn);
        const float4* pr = (const float4*)(pos + (size_t)m * Dn);
        float4 e[4];
        float dc = 0.f, en = 0.f, dp = 0.f;
#pragma unroll
        for (int j = 0; j < 4; j++) {
            e[j] = er[lane + 32 * j];
            float4 p = pr[lane + 32 * j];
            dc += dot4(e[j], q4[lane + 32 * j]);
            en += dot4(e[j], e[j]);
            dp += dot4(p, p4[lane + 32 * j]);
        }
        float send1 = (lane & 1) ? dc : en;
        float recv1 = __shfl_xor_sync(0xffffffffu, send1, 1);
        float v = ((lane & 1) ? en : dc) + recv1;
        float u = dp;
#pragma unroll
        for (int o = 2; o <= 16; o <<= 1) {
            v += __shfl_xor_sync(0xffffffffu, v, o);
            u += __shfl_xor_sync(0xffffffffu, u, o);
        }
        u += __shfl_xor_sync(0xffffffffu, u, 1);         // full dp sum
        float enq = __shfl_xor_sync(0xffffffffu, v, 1);  // even lanes: en sum
        float wgt = 0.f;
        if (lane == 0) {
            float inve = 1.0f / fmaxf(sqrtf(enq), 1.0f);
            float s = v * inve + u * g_inv_p[m];
            float ex = __expf(s * (1.0f / 32.0f));
            es += ex;
            wgt = ex * inve;
        }
        wgt = __shfl_sync(0xffffffffu, wgt, 0);
#pragma unroll
        for (int j = 0; j < 4; j++) {
            acc[j].x += wgt * e[j].x;
            acc[j].y += wgt * e[j].y;
            acc[j].z += wgt * e[j].z;
            acc[j].w += wgt * e[j].w;
        }
    }
#pragma unroll
    for (int j = 0; j < 4; j++) wacc[wid * 128 + lane + 32 * j] = acc[j];
    if (lane == 0) wes[wid] = es;
    __syncthreads();
    if (tid == 0) {
        float sw = 0.f;
#pragma unroll
        for (int i = 0; i < 16; i++) sw += wes[i];
        g_wpart[b * NCHUNK + c] = sw;
    }
    if (tid < 128) {
        float4 s = make_float4(0.f, 0.f, 0.f, 0.f);
#pragma unroll
        for (int w = 0; w < 16; w++) {
            float4 a = wacc[w * 128 + tid];
            s.x += a.x; s.y += a.y; s.z += a.z; s.w += a.w;
        }
        ((float4*)g_partial)[(size_t)(b * NCHUNK + c) * 128 + tid] = s;
    }
}

// ---------------- K2: reduce partials, normalize -> sel ----------------
__global__ __launch_bounds__(512) void k_sel(float* __restrict__ out_sel) {
    int b = blockIdx.x, tid = threadIdx.x;
    __shared__ float sinv;
    if (tid < 32) {
        float v = (tid < NCHUNK) ? g_wpart[b * NCHUNK + tid] : 0.f;
#pragma unroll
        for (int o = 16; o; o >>= 1) v += __shfl_xor_sync(0xffffffffu, v, o);
        if (tid == 0) sinv = 1.0f / v;
    }
    __syncthreads();
    float s = 0.f;
#pragma unroll
    for (int c = 0; c < NCHUNK; c++) s += g_partial[(b * NCHUNK + c) * Dn + tid];
    s *= sinv;
    g_sel[b * Dn + tid] = s;
    if (out_sel) out_sel[b * Dn + tid] = s;
}

// ---------------- K3: vocab inner products, cp.async-staged rows ---------
// grid NBLK=444 (3 blocks/SM, EXACTLY one wave), block 128 (4 warps).
// Grid-stride over NGRP=2000 groups of 16 tokens (224 blocks x5, 220 x4).
// Per group: cp.async the 16 emb rows (32KB) into smem; compute from smem.
// Next group's copies are issued during phase 2 (copy/compute overlap).
__global__ __launch_bounds__(128, 3) void k_ip(
    const float* __restrict__ emb, const int* __restrict__ x,
    const int* __restrict__ mask_idx) {
    extern __shared__ __align__(16) float smem[];
    float* rbuf = smem;                         // GTOK*Dn floats (32KB)
    float* part = smem + GTOK * Dn;             // (NORMROW+GTOK)*PSTRIDE
    int tid = threadIdx.x;
    int w = tid >> 5, lane = tid & 31;
    int b0 = w * 4;

    // issue first group's copies (overlap with selp loads)
    unsigned int rbase = (unsigned int)__cvta_generic_to_shared(rbuf);
    {
        const float* src = emb + (size_t)blockIdx.x * GTOK * Dn;
#pragma unroll
        for (int j = 0; j < 16; j++) {
            int idx = j * 128 + tid;
            CP_ASYNC16(rbase + idx * 16, (const float4*)src + idx);
        }
        CP_COMMIT();
    }

    // sel cache for this warp's 4 batches
    unsigned long long selp[4][8];
#pragma unroll
    for (int bb = 0; bb < 4; bb++) {
        const ulonglong2* s2 = (const ulonglong2*)(g_sel + (size_t)(b0 + bb) * Dn);
#pragma unroll
        for (int j = 0; j < 4; j++) {
            ulonglong2 q = s2[lane + 32 * j];
            selp[bb][2 * j] = q.x;
            selp[bb][2 * j + 1] = q.y;
        }
    }

    // phase-2 ownership: round k: row r = w*64 + k*32 + lane, b=r>>4, t=r&15
    int pb[2], ptgt[2];
    float es[2] = {0.f, 0.f};
#pragma unroll
    for (int k = 0; k < 2; k++) {
        int r = w * 64 + k * 32 + lane;
        pb[k] = r >> 4;
        ptgt[k] = x[pb[k] * Ln + mask_idx[pb[k]]];
    }
    int myt = lane & 15;   // token index within group for phase 2

#pragma unroll 1
    for (int gi = blockIdx.x; gi < NGRP; gi += NBLK) {
        int t0 = gi * GTOK;
        CP_WAIT0();
        __syncthreads();
        // ---- phase 1: compute from smem rows ----
        const ulonglong2* r2 = (const ulonglong2*)rbuf;
#pragma unroll 2
        for (int t = 0; t < GTOK; t++) {
            unsigned long long ep[8];
#pragma unroll
            for (int j = 0; j < 4; j++) {
                ulonglong2 q = r2[t * 128 + lane + 32 * j];
                ep[2 * j] = q.x;
                ep[2 * j + 1] = q.y;
            }
            unsigned long long acc2[4] = {0ull, 0ull, 0ull, 0ull};
#pragma unroll
            for (int j = 0; j < 8; j++) {
                FMA2(acc2[0], ep[j], selp[0][j]);
                FMA2(acc2[1], ep[j], selp[1][j]);
                FMA2(acc2[2], ep[j], selp[2][j]);
                FMA2(acc2[3], ep[j], selp[3][j]);
            }
#pragma unroll
            for (int bb = 0; bb < 4; bb++)
                part[((b0 + bb) * GTOK + t) * PSTRIDE + lane] =
                    unpack_add(acc2[bb]);
            if (w == (t & 3)) {   // norm partial: one warp per token
                unsigned long long nacc = 0ull;
#pragma unroll
                for (int j = 0; j < 8; j++) FMA2(nacc, ep[j], ep[j]);
                part[(NORMROW + t) * PSTRIDE + lane] = unpack_add(nacc);
            }
        }
        __syncthreads();   // part complete; rbuf no longer read
        // issue next group's copies (overlaps phase 2)
        int gnext = gi + NBLK;
        if (gnext < NGRP) {
            const float* src = emb + (size_t)gnext * GTOK * Dn;
#pragma unroll
            for (int j = 0; j < 16; j++) {
                int idx = j * 128 + tid;
                CP_ASYNC16(rbase + idx * 16, (const float4*)src + idx);
            }
            CP_COMMIT();
        }
        // ---- phase 2 ----
        float ninv;
        {
            const float4* nr = (const float4*)&part[(NORMROW + myt) * PSTRIDE];
            float4 n0 = nr[0], n1 = nr[1], n2 = nr[2], n3 = nr[3];
            float4 n4 = nr[4], n5 = nr[5], n6 = nr[6], n7 = nr[7];
            float nx = ((n0.x + n1.x) + (n2.x + n3.x)) + ((n4.x + n5.x) + (n6.x + n7.x));
            float ny = ((n0.y + n1.y) + (n2.y + n3.y)) + ((n4.y + n5.y) + (n6.y + n7.y));
            float nz = ((n0.z + n1.z) + (n2.z + n3.z)) + ((n4.z + n5.z) + (n6.z + n7.z));
            float nw = ((n0.w + n1.w) + (n2.w + n3.w)) + ((n4.w + n5.w) + (n6.w + n7.w));
            float nsum = (nx + ny) + (nz + nw);
            ninv = 1.0f / fmaxf(sqrtf(nsum), 1.0f);
        }
#pragma unroll
        for (int k = 0; k < 2; k++) {
            int r = w * 64 + k * 32 + lane;
            const float4* row = (const float4*)&part[r * PSTRIDE];
            float4 s0 = row[0], s1 = row[1], s2 = row[2], s3 = row[3];
            float4 s4 = row[4], s5 = row[5], s6 = row[6], s7 = row[7];
            float4 u;
            u.x = ((s0.x + s1.x) + (s2.x + s3.x)) + ((s4.x + s5.x) + (s6.x + s7.x));
            u.y = ((s0.y + s1.y) + (s2.y + s3.y)) + ((s4.y + s5.y) + (s6.y + s7.y));
            u.z = ((s0.z + s1.z) + (s2.z + s3.z)) + ((s4.z + s5.z) + (s6.z + s7.z));
            u.w = ((s0.w + s1.w) + (s2.w + s3.w)) + ((s4.w + s5.w) + (s6.w + s7.w));
            float dot = (u.x + u.y) + (u.z + u.w);
            int tok = t0 + myt;
            float v = dot * ninv;
            if (tok == ptgt[k]) g_tgtip[pb[k]] = v;
            es[k] += __expf(v);
        }
        __syncthreads();   // part free before next phase 1 writes
    }
    // block-level exp-sum: 16 lanes share each (round, half) batch
#pragma unroll
    for (int k = 0; k < 2; k++) {
        float e = es[k];
#pragma unroll
        for (int o = 8; o; o >>= 1) e += __shfl_xor_sync(0xffffffffu, e, o);
        if ((lane & 15) == 0) g_esum[pb[k] * ESTRIDE + blockIdx.x] = e;
    }
}

// ---------------- K4: final loss ----------------
__global__ __launch_bounds__(512) void k_final(float* __restrict__ out_loss) {
    __shared__ float lp[16];
    int w = threadIdx.x >> 5, lane = threadIdx.x & 31;   // 16 warps, warp per b
    const float4* p = (const float4*)&g_esum[w * ESTRIDE];
    float s = 0.f;
#pragma unroll
    for (int q = 0; q < 4; q++) {
        float4 v = p[lane + 32 * q];
        s += (v.x + v.y) + (v.z + v.w);
    }
#pragma unroll
    for (int o = 16; o; o >>= 1) s += __shfl_xor_sync(0xffffffffu, s, o);
    if (lane == 0) lp[w] = g_tgtip[w] - logf(s);
    __syncthreads();
    if (threadIdx.x == 0) {
        float t = 0.f;
#pragma unroll
        for (int b = 0; b < Bn; b++) t += lp[b];
        if (out_loss) *out_loss = -t * (1.0f / Bn);
    }
}

// ---------------- host ----------------
extern "C" void kernel_launch(void* const* d_in, const int* in_sizes, int n_in,
                              void* d_out, int out_size) {
    const int* x = nullptr;
    const int* mask_idx = nullptr;
    const float* emb = nullptr;
    const float* pos = nullptr;
    for (int i = 0; i < n_in; i++) {
        switch (in_sizes[i]) {
            case Bn * Ln:        x = (const int*)d_in[i]; break;
            case Bn:             mask_idx = (const int*)d_in[i]; break;
            case (Mn + 1) * Dn:  emb = (const float*)d_in[i]; break;
            case Ln * Dn:        pos = (const float*)d_in[i]; break;
            default: break;
        }
    }

    float* out = (float*)d_out;
    float* lossp;
    float* selp;
    if (out_size == 1 + Bn * Dn) { lossp = out; selp = out + 1; }
    else if (out_size == Bn * Dn) { lossp = nullptr; selp = out; }
    else if (out_size == 1) { lossp = out; selp = nullptr; }
    else { lossp = out; selp = (out_size > 1) ? out + 1 : nullptr; }

    cudaFuncSetAttribute(k_ip, cudaFuncAttributeMaxDynamicSharedMemorySize,
                         IP_SMEM);

    // K0: pos + q-row inverse norms
    {
        int totalWarps = Ln + 1;
        int blocks = (totalWarps * 32 + 255) / 256;
        k_pnorm<<<blocks, 256>>>(emb, pos);
    }
    // K1: fused logits + emb norms + exp + weighted-sum (single row touch)
    {
        dim3 g(NCHUNK, Bn);
        k24<<<g, 512>>>(emb, pos, x, mask_idx);
    }
    // K2: reduce -> sel_output
    k_sel<<<Bn, 512>>>(selp);
    // K3: vocab inner products (cp.async staged, single wave) + exp-sums
    k_ip<<<NBLK, 128, IP_SMEM>>>(emb, x, mask_idx);
    // K4: final loss
    k_final<<<1, 512>>>(lossp);
}